// round 7
// baseline (speedup 1.0000x reference)
#include <cuda_runtime.h>
#include <cuda_bf16.h>
#include <math.h>
#include <stdint.h>

namespace {
constexpr int Bb = 4096, Dd = 64, Cc = 16, Hh = 512, NB = 2, NS = 8;
constexpr int SAS = 40;              // smem row stride in halves (80B)
constexpr int PT = 128 * SAS;        // halves per buffer per plane
constexpr int NBUF = 3;
constexpr int SMEM_BYTES = 4 * NBUF * PT * 2 + 128 * 4 * 4;  // 4 planes x 3 bufs + red
}

// ---------------- device scratch ----------------
__device__ __align__(16) __nv_bfloat16 g_h1h[Bb * Hh], g_h1l[Bb * Hh];
__device__ __align__(16) __nv_bfloat16 g_mAh[Bb * Hh], g_mAl[Bb * Hh];   // masked B2 A planes
__device__ __align__(16) float g_h2f[Bb * Hh];                            // fp32 h2 for F3
__device__ __align__(16) __nv_bfloat16 g_yinh[Bb * Dd], g_yinl[Bb * Dd];
__device__ __align__(16) float g_y[Bb * Dd], g_yacc[Bb * Dd];
__device__ __align__(16) float g_cb[NB * Bb * Hh], g_G3[NB * Bb * Hh], g_E1[NB * Bb * Hh];
__device__ __align__(16) float g_ld[Bb], g_psum[4 * Bb];
__device__ __align__(16) __nv_bfloat16 g_epsh[NB * Bb * Dd],  g_epsl[NB * Bb * Dd];
__device__ __align__(16) __nv_bfloat16 g_W2h [NB * Hh * Hh],  g_W2l [NB * Hh * Hh];   // [n][k] B2
__device__ __align__(16) __nv_bfloat16 g_W2Th[NB * Hh * Hh],  g_W2Tl[NB * Hh * Hh];   // [n][k] F2
__device__ __align__(16) __nv_bfloat16 g_W3h [NB * Hh * Dd],  g_W3l [NB * Hh * Dd];   // [512][64] G3
__device__ __align__(16) __nv_bfloat16 g_W1yTh[NB * Hh * Dd], g_W1yTl[NB * Hh * Dd];  // [512][64] F1/E1

// ---------------- helpers ----------------
__device__ __forceinline__ uint32_t sptr(const void* p) {
    return (uint32_t)__cvta_generic_to_shared(p);
}
__device__ __forceinline__ void ldm4(uint32_t a, uint32_t& r0, uint32_t& r1,
                                     uint32_t& r2, uint32_t& r3) {
    asm volatile("ldmatrix.sync.aligned.m8n8.x4.shared.b16 {%0,%1,%2,%3}, [%4];"
                 : "=r"(r0), "=r"(r1), "=r"(r2), "=r"(r3) : "r"(a));
}
__device__ __forceinline__ void mma_bf16(float* c, const uint32_t* a, uint32_t b0, uint32_t b1) {
    asm volatile("mma.sync.aligned.m16n8k16.row.col.f32.bf16.bf16.f32 "
                 "{%0,%1,%2,%3}, {%4,%5,%6,%7}, {%8,%9}, {%0,%1,%2,%3};"
                 : "+f"(c[0]), "+f"(c[1]), "+f"(c[2]), "+f"(c[3])
                 : "r"(a[0]), "r"(a[1]), "r"(a[2]), "r"(a[3]), "r"(b0), "r"(b1));
}
__device__ __forceinline__ void cp16(void* dst, const void* src) {
    asm volatile("cp.async.cg.shared.global [%0], [%1], 16;"
                 :: "r"(sptr(dst)), "l"(src));
}
#define CP_COMMIT() asm volatile("cp.async.commit_group;" ::: "memory")
#define CP_WAIT1()  asm volatile("cp.async.wait_group 1;" ::: "memory")

__device__ __forceinline__ unsigned pack_split2(float v0, float v1, unsigned& lo_out) {
    __nv_bfloat16 h0 = __float2bfloat16(v0), h1 = __float2bfloat16(v1);
    __nv_bfloat16 l0 = __float2bfloat16(v0 - __bfloat162float(h0));
    __nv_bfloat16 l1 = __float2bfloat16(v1 - __bfloat162float(h1));
    lo_out = (unsigned)__bfloat16_as_ushort(l0) | ((unsigned)__bfloat16_as_ushort(l1) << 16);
    return (unsigned)__bfloat16_as_ushort(h0) | ((unsigned)__bfloat16_as_ushort(h1) << 16);
}
__device__ __forceinline__ float bf2sum(unsigned hi, unsigned lo, int half) {
    unsigned short h = (unsigned short)(half ? (hi >> 16) : hi);
    unsigned short l = (unsigned short)(half ? (lo >> 16) : lo);
    return __bfloat162float(__ushort_as_bfloat16(h)) + __bfloat162float(__ushort_as_bfloat16(l));
}
__device__ __forceinline__ float ftanh(float x) {
    const float cx = fminf(fmaxf(x, -15.f), 15.f);
    const float e = __expf(2.f * cx);
    return __fdividef(e - 1.f, e + 1.f);
}

struct P {
    const __nv_bfloat16 *Ah, *Al, *Bh, *Bl, *B2h, *B2l;
    const float *Amask;               // G3 (for F2 mask epilogue)
    const float *h2f, *W3f;           // F3 fp32 operands
    float *C, *C2;                    // fp32 outputs (MODE 0), h2f32 out (MODE 2)
    const float *cbias, *w1t, *bias, *b3, *E1;
    const __nv_bfloat16 *h1h, *h1l;
    __nv_bfloat16 *Oh, *Ol;           // bf16 plane outputs
    float *y, *yacc, *ld, *psum;
    int stage;
    float t, cacc, cin, foldcoef;
};

// MODE 0: by<4 G3 / by>=4 E1 (K=64, fp32 C)                          grid (32,8)
// MODE 1: F1 (K=64, tanh epi -> h1 planes); by==0 also folds psum    grid (32,4)
// MODE 2: F2 (K=512, tanh epi -> h2f32 + masked mA planes)           grid (32,4)
// MODE 3: B2 (K=512, logdet dot -> psum) then fp32 SIMT F3 + RK4     grid (32,4)
template <int MODE>
__global__ void __launch_bounds__(512, 1) mma_k(P p) {
    extern __shared__ __align__(16) char dynsmem[];
    __nv_bfloat16* sAh = (__nv_bfloat16*)dynsmem;
    __nv_bfloat16* sAl = sAh + NBUF * PT;
    __nv_bfloat16* sBh = sAl + NBUF * PT;
    __nv_bfloat16* sBl = sBh + NBUF * PT;
    float* red = (float*)(sBl + NBUF * PT);

    const int tid = threadIdx.x, lane = tid & 31, wid = tid >> 5;
    const int wm = wid & 3, wn = wid >> 2;
    const int m0 = blockIdx.x * 128, by = blockIdx.y;

    if (MODE == 1 && by == 0 && p.foldcoef != 0.f) {   // fold previous logdet partials
        if (tid < 128) {
            const int m = m0 + tid;
            float s = 0.f;
            #pragma unroll
            for (int c = 0; c < 4; c++) s += p.psum[c * Bb + m];
            p.ld[m] += p.foldcoef * s;
        }
    }

    // ---- operand resolve ----
    const __nv_bfloat16 *Ah = p.Ah, *Al = p.Al, *Bhp, *Blp;
    int lda, K, n0;
    float* C0 = nullptr;
    if (MODE == 0) {
        K = 64; lda = 64;
        if (by < 4) { Bhp = p.Bh; Blp = p.Bl; C0 = p.C; n0 = by * 128; }
        else        { Bhp = p.B2h; Blp = p.B2l; C0 = p.C2; n0 = (by - 4) * 128; }
    } else if (MODE == 1) {
        K = 64; lda = 64; n0 = by * 128; Bhp = p.Bh; Blp = p.Bl;
    } else {
        K = 512; lda = 512; n0 = by * 128; Bhp = p.Bh; Blp = p.Bl;
    }
    const int ldb = lda;
    const int NT = K / 32;

    auto issue = [&](int kt) {
        if (kt < NT) {
            const int buf = kt % 3;
            const int k0 = kt * 32;
            #pragma unroll
            for (int c = tid; c < 1024; c += 512) {
                const int plane = c >> 9, cc = c & 511;
                const int row = cc >> 2, ku = cc & 3;
                cp16((plane ? sAl : sAh) + buf * PT + row * SAS + ku * 8,
                     (plane ? Al : Ah) + (size_t)(m0 + row) * lda + k0 + ku * 8);
            }
            #pragma unroll
            for (int c = tid; c < 1024; c += 512) {
                const int plane = c >> 9, cc = c & 511;
                const int row = cc >> 2, ku = cc & 3;
                cp16((plane ? sBl : sBh) + buf * PT + row * SAS + ku * 8,
                     (plane ? Blp : Bhp) + (size_t)(n0 + row) * ldb + k0 + ku * 8);
            }
        }
        CP_COMMIT();
    };

    // fragment addressing
    const int l7 = lane & 7;
    const int aro = l7 + ((lane >> 3) & 1) * 8;
    const int aco = (lane >> 4) * 8;
    const int bro = l7 + (lane >> 4) * 8;
    const int bco = ((lane >> 3) & 1) * 8;

    float acc[2][4][4] = {};

    auto compute = [&](int buf) {
        const uint32_t bAh = sptr(sAh + buf * PT);
        const uint32_t bAl = sptr(sAl + buf * PT);
        const uint32_t bBh = sptr(sBh + buf * PT);
        const uint32_t bBl = sptr(sBl + buf * PT);
        #pragma unroll
        for (int kk = 0; kk < 2; kk++) {
            uint32_t ah[2][4], al[2][4], bh[2][4], bl[2][4];
            #pragma unroll
            for (int mt = 0; mt < 2; mt++) {
                const uint32_t off = ((wm * 32 + mt * 16 + aro) * SAS + kk * 16 + aco) * 2;
                ldm4(bAh + off, ah[mt][0], ah[mt][1], ah[mt][2], ah[mt][3]);
                ldm4(bAl + off, al[mt][0], al[mt][1], al[mt][2], al[mt][3]);
            }
            #pragma unroll
            for (int pn = 0; pn < 2; pn++) {
                const uint32_t off = ((wn * 32 + pn * 16 + bro) * SAS + kk * 16 + bco) * 2;
                ldm4(bBh + off, bh[pn][0], bh[pn][1], bh[pn][2], bh[pn][3]);
                ldm4(bBl + off, bl[pn][0], bl[pn][1], bl[pn][2], bl[pn][3]);
            }
            #pragma unroll
            for (int mt = 0; mt < 2; mt++)
                #pragma unroll
                for (int nt = 0; nt < 4; nt++) {
                    const uint32_t b0h = bh[nt >> 1][(nt & 1) * 2], b1h = bh[nt >> 1][(nt & 1) * 2 + 1];
                    const uint32_t b0l = bl[nt >> 1][(nt & 1) * 2], b1l = bl[nt >> 1][(nt & 1) * 2 + 1];
                    mma_bf16(acc[mt][nt], ah[mt], b0h, b1h);
                    mma_bf16(acc[mt][nt], ah[mt], b0l, b1l);
                    mma_bf16(acc[mt][nt], al[mt], b0h, b1h);
                }
        }
    };

    issue(0);
    issue(1);
    for (int kt = 0; kt < NT; kt++) {
        CP_WAIT1();
        __syncthreads();
        issue(kt + 2);
        compute(kt % 3);
    }

    // ---- epilogues ----
    const int g = lane >> 2, tt = lane & 3;

    if (MODE == 3) {
        // B2 logdet dot -> psum
        float s[4] = {0.f, 0.f, 0.f, 0.f};
        #pragma unroll
        for (int mt = 0; mt < 2; mt++)
            #pragma unroll
            for (int nt = 0; nt < 4; nt++) {
                const int c = n0 + wn * 32 + nt * 8 + tt * 2;
                #pragma unroll
                for (int hr = 0; hr < 2; hr++) {
                    const int r = m0 + wm * 32 + mt * 16 + g + hr * 8;
                    const size_t off = (size_t)r * 512 + c;
                    const unsigned hh = *(const unsigned*)&p.h1h[off];
                    const unsigned hl = *(const unsigned*)&p.h1l[off];
                    const float2 e = *(const float2*)&p.E1[off];
                    const float h0 = bf2sum(hh, hl, 0), h1v = bf2sum(hh, hl, 1);
                    s[mt * 2 + hr] += acc[mt][nt][hr * 2 + 0] * (1.f - h0 * h0) * e.x
                                    + acc[mt][nt][hr * 2 + 1] * (1.f - h1v * h1v) * e.y;
                }
            }
        #pragma unroll
        for (int i = 0; i < 4; i++) {
            s[i] += __shfl_xor_sync(0xffffffffu, s[i], 1);
            s[i] += __shfl_xor_sync(0xffffffffu, s[i], 2);
        }
        __syncthreads();   // mainloop smem reads done before red overwrite below is seen uniformly
        if (tt == 0) {
            #pragma unroll
            for (int mt = 0; mt < 2; mt++)
                #pragma unroll
                for (int hr = 0; hr < 2; hr++)
                    red[(wm * 32 + mt * 16 + g + hr * 8) * 4 + wn] = s[mt * 2 + hr];
        }
        __syncthreads();
        if (tid < 128) {
            const float* r4 = red + tid * 4;
            p.psum[(size_t)by * Bb + m0 + tid] = (r4[0] + r4[1]) + (r4[2] + r4[3]);
        }
        __syncthreads();

        // ---- fp32 SIMT F3 chunk: rows [m0 + by*32, +32), N=64, K=512 ----
        float* fA = (float*)dynsmem;          // 32 x 128 fp32
        float* fB = fA + 32 * 128;            // 128 x 64 fp32
        const int r0 = m0 + by * 32;
        const int rr = tid >> 4, ccq = (tid & 15) * 4;
        float accf[4] = {0.f, 0.f, 0.f, 0.f};
        #pragma unroll
        for (int t4 = 0; t4 < 4; t4++) {
            const int k0 = t4 * 128;
            #pragma unroll
            for (int i = tid; i < 1024; i += 512) {
                const int row = i >> 5, kq = i & 31;
                *(float4*)&fA[row * 128 + kq * 4] =
                    *(const float4*)&p.h2f[(size_t)(r0 + row) * 512 + k0 + kq * 4];
            }
            #pragma unroll
            for (int i = tid; i < 2048; i += 512) {
                const int row = i >> 4, cq = i & 15;
                *(float4*)&fB[row * 64 + cq * 4] =
                    *(const float4*)&p.W3f[(size_t)(k0 + row) * 64 + cq * 4];
            }
            __syncthreads();
            #pragma unroll 4
            for (int k = 0; k < 128; k++) {
                const float a = fA[rr * 128 + k];
                const float4 b = *(const float4*)&fB[k * 64 + ccq];
                accf[0] = fmaf(a, b.x, accf[0]);
                accf[1] = fmaf(a, b.y, accf[1]);
                accf[2] = fmaf(a, b.z, accf[2]);
                accf[3] = fmaf(a, b.w, accf[3]);
            }
            __syncthreads();
        }
        // RK4 state update
        {
            const int r = r0 + rr;
            const size_t idx = (size_t)r * 64 + ccq;
            const float4 b3v = *(const float4*)&p.b3[ccq];
            float kv[4] = {accf[0] + b3v.x, accf[1] + b3v.y, accf[2] + b3v.z, accf[3] + b3v.w};
            const float4 base = (p.stage == 1) ? *(const float4*)&p.y[idx]
                                               : *(const float4*)&p.yacc[idx];
            float ya[4] = {base.x + p.cacc * kv[0], base.y + p.cacc * kv[1],
                           base.z + p.cacc * kv[2], base.w + p.cacc * kv[3]};
            float yi[4];
            if (p.stage == 4) {
                *(float4*)&p.y[idx] = make_float4(ya[0], ya[1], ya[2], ya[3]);
                yi[0] = ya[0]; yi[1] = ya[1]; yi[2] = ya[2]; yi[3] = ya[3];
            } else {
                *(float4*)&p.yacc[idx] = make_float4(ya[0], ya[1], ya[2], ya[3]);
                const float4 yv = *(const float4*)&p.y[idx];
                yi[0] = yv.x + p.cin * kv[0]; yi[1] = yv.y + p.cin * kv[1];
                yi[2] = yv.z + p.cin * kv[2]; yi[3] = yv.w + p.cin * kv[3];
            }
            uint2 hi, lo;
            hi.x = pack_split2(yi[0], yi[1], lo.x);
            hi.y = pack_split2(yi[2], yi[3], lo.y);
            *(uint2*)&((unsigned*)p.Oh)[idx >> 1] = hi;
            *(uint2*)&((unsigned*)p.Ol)[idx >> 1] = lo;
        }
        return;
    }

    // MODE 0/1/2 fragment epilogues
    #pragma unroll
    for (int mt = 0; mt < 2; mt++)
        #pragma unroll
        for (int nt = 0; nt < 4; nt++) {
            const int c = n0 + wn * 32 + nt * 8 + tt * 2;
            #pragma unroll
            for (int hr = 0; hr < 2; hr++) {
                const int r = m0 + wm * 32 + mt * 16 + g + hr * 8;
                float v0 = acc[mt][nt][hr * 2 + 0];
                float v1 = acc[mt][nt][hr * 2 + 1];
                const size_t off = (size_t)r * 512 + c;
                if (MODE == 0) {
                    *(float2*)&C0[off] = make_float2(v0, v1);
                } else if (MODE == 1) {
                    const float2 cb = *(const float2*)&p.cbias[off];
                    const float2 wt = *(const float2*)&p.w1t[c];
                    v0 = ftanh(v0 + cb.x + p.t * wt.x);
                    v1 = ftanh(v1 + cb.y + p.t * wt.y);
                    unsigned lo, hi = pack_split2(v0, v1, lo);
                    ((unsigned*)p.Oh)[off >> 1] = hi;
                    ((unsigned*)p.Ol)[off >> 1] = lo;
                } else {   // MODE 2: tanh -> h2f32 + masked mA planes
                    const float2 bi = *(const float2*)&p.bias[c];
                    v0 = ftanh(v0 + bi.x);
                    v1 = ftanh(v1 + bi.y);
                    *(float2*)&p.C[off] = make_float2(v0, v1);
                    const float2 gv = *(const float2*)&p.Amask[off];
                    const float m0v = gv.x * (1.f - v0 * v0);
                    const float m1v = gv.y * (1.f - v1 * v1);
                    unsigned lo, hi = pack_split2(m0v, m1v, lo);
                    ((unsigned*)p.Oh)[off >> 1] = hi;
                    ((unsigned*)p.Ol)[off >> 1] = lo;
                }
            }
        }
}

// ---------------- aux kernels ----------------
__device__ __forceinline__ void wsplit(float v, __nv_bfloat16* h, __nv_bfloat16* l, size_t i) {
    const __nv_bfloat16 hv = __float2bfloat16(v);
    h[i] = hv;
    l[i] = __float2bfloat16(v - __bfloat162float(hv));
}
__global__ void prep_k(const float* __restrict__ eps, const float* __restrict__ W2,
                       const float* __restrict__ W3, const float* __restrict__ W1,
                       __nv_bfloat16* eph, __nv_bfloat16* epl,
                       __nv_bfloat16* w2h, __nv_bfloat16* w2l,
                       __nv_bfloat16* w3h, __nv_bfloat16* w3l,
                       __nv_bfloat16* w2th, __nv_bfloat16* w2tl,
                       __nv_bfloat16* w1yth, __nv_bfloat16* w1ytl) {
    int i = blockIdx.x * 256 + threadIdx.x;
    if (i < Bb * Dd) { wsplit(eps[i], eph, epl, i); return; }
    i -= Bb * Dd;
    if (i < Hh * Hh) { wsplit(W2[i], w2h, w2l, i); return; }
    i -= Hh * Hh;
    if (i < Hh * Dd) { wsplit(W3[i], w3h, w3l, i); return; }
    i -= Hh * Dd;
    if (i < Hh * Hh) {
        const int r = i / Hh, c = i % Hh;
        wsplit(W2[i], w2th, w2tl, (size_t)c * Hh + r);
        return;
    }
    i -= Hh * Hh;
    if (i < Dd * Hh) {
        const int r = i / Hh, c = i % Hh;
        wsplit(W1[i], w1yth, w1ytl, (size_t)c * Dd + r);
    }
}
__global__ void cbias_k(const float* __restrict__ cond, const float* __restrict__ W1c,
                        const float* __restrict__ b1, float* __restrict__ cb) {
    const int m = blockIdx.x;
    const int n = threadIdx.x * 4;
    float4 acc = *(const float4*)(b1 + n);
    #pragma unroll
    for (int k = 0; k < Cc; k++) {
        const float c = cond[m * Cc + k];
        const float4 w = *(const float4*)(W1c + (size_t)k * Hh + n);
        acc.x = fmaf(c, w.x, acc.x); acc.y = fmaf(c, w.y, acc.y);
        acc.z = fmaf(c, w.z, acc.z); acc.w = fmaf(c, w.w, acc.w);
    }
    *(float4*)(cb + (size_t)m * Hh + n) = acc;
}
__global__ void init_k(const float* __restrict__ x, float* __restrict__ y,
                       __nv_bfloat16* __restrict__ yinh, __nv_bfloat16* __restrict__ yinl,
                       float* __restrict__ ld) {
    const int i = blockIdx.x * blockDim.x + threadIdx.x;
    if (i < Bb * Dd) {
        const float v = x[i];
        y[i] = v;
        wsplit(v, yinh, yinl, i);
    }
    if (i < Bb) ld[i] = 0.f;
}
__global__ void out_k(const float* __restrict__ y, const float* __restrict__ ld,
                      const float* __restrict__ psum, float coef, float* __restrict__ out) {
    const int i = blockIdx.x * blockDim.x + threadIdx.x;
    if (i >= Bb * (Dd + 1)) return;
    const int m = i / (Dd + 1), c = i % (Dd + 1);
    if (c < Dd) {
        out[i] = y[(size_t)m * Dd + c];
    } else {
        float s = 0.f;
        #pragma unroll
        for (int c2 = 0; c2 < 4; c2++) s += psum[c2 * Bb + m];
        out[i] = ld[m] + coef * s;
    }
}

// ---------------- host ----------------
extern "C" void kernel_launch(void* const* d_in, const int* in_sizes, int n_in,
                              void* d_out, int out_size) {
    const float* x    = (const float*)d_in[0];
    const float* cond = (const float*)d_in[1];
    const float* eps  = (const float*)d_in[2];
    const float* W1   = (const float*)d_in[3];
    const float* b1   = (const float*)d_in[4];
    const float* W2   = (const float*)d_in[5];
    const float* b2   = (const float*)d_in[6];
    const float* W3   = (const float*)d_in[7];
    const float* b3   = (const float*)d_in[8];
    float* out = (float*)d_out;

    cudaFuncSetAttribute(mma_k<0>, cudaFuncAttributeMaxDynamicSharedMemorySize, SMEM_BYTES);
    cudaFuncSetAttribute(mma_k<1>, cudaFuncAttributeMaxDynamicSharedMemorySize, SMEM_BYTES);
    cudaFuncSetAttribute(mma_k<2>, cudaFuncAttributeMaxDynamicSharedMemorySize, SMEM_BYTES);
    cudaFuncSetAttribute(mma_k<3>, cudaFuncAttributeMaxDynamicSharedMemorySize, SMEM_BYTES);

    #define SYM(T, v, s) T* v; { void* _p; cudaGetSymbolAddress(&_p, s); v = (T*)_p; }
    SYM(float, y, g_y) SYM(float, yacc, g_yacc) SYM(float, cb, g_cb)
    SYM(float, G3, g_G3) SYM(float, E1, g_E1) SYM(float, ld, g_ld) SYM(float, psum, g_psum)
    SYM(float, h2f, g_h2f)
    SYM(__nv_bfloat16, h1h, g_h1h) SYM(__nv_bfloat16, h1l, g_h1l)
    SYM(__nv_bfloat16, mAh, g_mAh) SYM(__nv_bfloat16, mAl, g_mAl)
    SYM(__nv_bfloat16, yinh, g_yinh) SYM(__nv_bfloat16, yinl, g_yinl)
    SYM(__nv_bfloat16, epsh, g_epsh) SYM(__nv_bfloat16, epsl, g_epsl)
    SYM(__nv_bfloat16, W2h, g_W2h) SYM(__nv_bfloat16, W2l, g_W2l)
    SYM(__nv_bfloat16, W2Th, g_W2Th) SYM(__nv_bfloat16, W2Tl, g_W2Tl)
    SYM(__nv_bfloat16, W3h, g_W3h) SYM(__nv_bfloat16, W3l, g_W3l)
    SYM(__nv_bfloat16, W1yTh, g_W1yTh) SYM(__nv_bfloat16, W1yTl, g_W1yTl)
    #undef SYM

    init_k<<<(Bb * Dd + 255) / 256, 256>>>(x, y, yinh, yinl, ld);

    constexpr int PREP_N = Bb * Dd + Hh * Hh + Hh * Dd + Hh * Hh + Dd * Hh;
    const float dt = 1.0f / NS;
    float prev_cl = 0.f;

    for (int ib = 0; ib < NB; ib++) {
        const float* W1b  = W1 + (size_t)ib * (Dd + Cc + 1) * Hh;
        const float* b1b  = b1 + (size_t)ib * Hh;
        const float* W2b  = W2 + (size_t)ib * Hh * Hh;
        const float* b2b  = b2 + (size_t)ib * Hh;
        const float* W3b  = W3 + (size_t)ib * Hh * Dd;
        const float* b3b  = b3 + (size_t)ib * Dd;
        const float* epsb = eps + (size_t)ib * Bb * Dd;
        float* cbb = cb + (size_t)ib * Bb * Hh;
        float* G3b = G3 + (size_t)ib * Bb * Hh;
        float* E1b = E1 + (size_t)ib * Bb * Hh;
        __nv_bfloat16 *eph = epsh + (size_t)ib * Bb * Dd, *epl = epsl + (size_t)ib * Bb * Dd;
        __nv_bfloat16 *w2h = W2h + (size_t)ib * Hh * Hh, *w2l = W2l + (size_t)ib * Hh * Hh;
        __nv_bfloat16 *w2th = W2Th + (size_t)ib * Hh * Hh, *w2tl = W2Tl + (size_t)ib * Hh * Hh;
        __nv_bfloat16 *w3h = W3h + (size_t)ib * Hh * Dd, *w3l = W3l + (size_t)ib * Hh * Dd;
        __nv_bfloat16 *w1yth = W1yTh + (size_t)ib * Hh * Dd, *w1ytl = W1yTl + (size_t)ib * Hh * Dd;

        prep_k<<<(PREP_N + 255) / 256, 256>>>(epsb, W2b, W3b, W1b,
            eph, epl, w2h, w2l, w3h, w3l, w2th, w2tl, w1yth, w1ytl);
        cbias_k<<<Bb, 128>>>(cond, W1b + (size_t)Dd * Hh, b1b, cbb);

        {   // merged G3 (by<4) + E1 (by>=4)
            P p{}; p.Ah = eph; p.Al = epl;
            p.Bh = w3h; p.Bl = w3l; p.C = G3b;
            p.B2h = w1yth; p.B2l = w1ytl; p.C2 = E1b;
            mma_k<0><<<dim3(32, 8), 512, SMEM_BYTES>>>(p);
        }

        for (int is = 0; is < NS; is++) {
            const float tbase = is * dt;
            for (int st = 1; st <= 4; st++) {
                const float t = tbase + (st == 1 ? 0.f : (st == 4 ? dt : 0.5f * dt));
                const float cacc = (st == 1 || st == 4) ? dt / 6.f : dt / 3.f;
                const float cin  = (st == 3) ? dt : 0.5f * dt;

                {   // F1 (+ fold in by==0)
                    P p{}; p.Ah = yinh; p.Al = yinl; p.Bh = w1yth; p.Bl = w1ytl;
                    p.cbias = cbb; p.w1t = W1b + (size_t)(Dd + Cc) * Hh; p.t = t;
                    p.Oh = h1h; p.Ol = h1l;
                    p.foldcoef = prev_cl; p.ld = ld; p.psum = psum;
                    mma_k<1><<<dim3(32, 4), 512, SMEM_BYTES>>>(p);
                }
                {   // F2: h2f32 + masked mA planes
                    P p{}; p.Ah = h1h; p.Al = h1l; p.Bh = w2th; p.Bl = w2tl;
                    p.bias = b2b; p.C = h2f; p.Amask = G3b;
                    p.Oh = mAh; p.Ol = mAl;
                    mma_k<2><<<dim3(32, 4), 512, SMEM_BYTES>>>(p);
                }
                {   // FUSED: B2 + logdet dot, then fp32 F3 chunk + RK4
                    P p{}; p.Ah = mAh; p.Al = mAl; p.Bh = w2h; p.Bl = w2l;
                    p.h1h = h1h; p.h1l = h1l; p.E1 = E1b; p.psum = psum;
                    p.h2f = h2f; p.W3f = W3b; p.b3 = b3b;
                    p.y = y; p.yacc = yacc; p.Oh = yinh; p.Ol = yinl;
                    p.stage = st; p.cacc = cacc; p.cin = cin;
                    mma_k<3><<<dim3(32, 4), 512, SMEM_BYTES>>>(p);
                }
                prev_cl = cacc;
            }
        }
    }

    out_k<<<(Bb * (Dd + 1) + 255) / 256, 256>>>(y, ld, psum, prev_cl, out);
}

// round 8
// speedup vs baseline: 1.2386x; 1.2386x over previous
#include <cuda_runtime.h>
#include <cuda_bf16.h>
#include <math.h>
#include <stdint.h>

namespace {
constexpr int Bb = 4096, Dd = 64, Cc = 16, Hh = 512, NB = 2, NS = 8;
constexpr int SAS = 40;               // smem row stride in halves (80B)
constexpr int AT = 128 * SAS;         // A halves per buffer
constexpr int BT = 64 * SAS;          // B halves per buffer
constexpr int SMEM_BYTES = (2 * AT + 2 * AT + 2 * BT + 2 * BT) * 2 + 256 * 4;
}

// ---------------- device scratch ----------------
__device__ __align__(16) __nv_bfloat16 g_h1h[Bb * Hh], g_h1l[Bb * Hh];
__device__ __align__(16) __nv_bfloat16 g_h2h[Bb * Hh], g_h2l[Bb * Hh];
__device__ __align__(16) __nv_bfloat16 g_yinh[Bb * Dd], g_yinl[Bb * Dd];
__device__ __align__(16) float g_y[Bb * Dd], g_yacc[Bb * Dd];
__device__ __align__(16) float g_cb[NB * Bb * Hh], g_G3[NB * Bb * Hh], g_E1[NB * Bb * Hh];
__device__ __align__(16) float g_ld[Bb], g_psum[8 * Bb];
__device__ __align__(16) __nv_bfloat16 g_epsh[NB * Bb * Dd],  g_epsl[NB * Bb * Dd];
__device__ __align__(16) __nv_bfloat16 g_W2h [NB * Hh * Hh],  g_W2l [NB * Hh * Hh];   // [n][k] B2
__device__ __align__(16) __nv_bfloat16 g_W2Th[NB * Hh * Hh],  g_W2Tl[NB * Hh * Hh];   // [n][k] F2
__device__ __align__(16) __nv_bfloat16 g_W3h [NB * Hh * Dd],  g_W3l [NB * Hh * Dd];   // [512][64] G3
__device__ __align__(16) __nv_bfloat16 g_W3Th[NB * Dd * Hh],  g_W3Tl[NB * Dd * Hh];   // [64][512] F3
__device__ __align__(16) __nv_bfloat16 g_W1yTh[NB * Hh * Dd], g_W1yTl[NB * Hh * Dd];  // [512][64] F1/E1

// ---------------- helpers ----------------
__device__ __forceinline__ uint32_t sptr(const void* p) {
    return (uint32_t)__cvta_generic_to_shared(p);
}
__device__ __forceinline__ void ldm4(uint32_t a, uint32_t& r0, uint32_t& r1,
                                     uint32_t& r2, uint32_t& r3) {
    asm volatile("ldmatrix.sync.aligned.m8n8.x4.shared.b16 {%0,%1,%2,%3}, [%4];"
                 : "=r"(r0), "=r"(r1), "=r"(r2), "=r"(r3) : "r"(a));
}
__device__ __forceinline__ void mma_bf16(float* c, const uint32_t* a, uint32_t b0, uint32_t b1) {
    asm volatile("mma.sync.aligned.m16n8k16.row.col.f32.bf16.bf16.f32 "
                 "{%0,%1,%2,%3}, {%4,%5,%6,%7}, {%8,%9}, {%0,%1,%2,%3};"
                 : "+f"(c[0]), "+f"(c[1]), "+f"(c[2]), "+f"(c[3])
                 : "r"(a[0]), "r"(a[1]), "r"(a[2]), "r"(a[3]), "r"(b0), "r"(b1));
}
__device__ __forceinline__ void cp16(void* dst, const void* src) {
    asm volatile("cp.async.cg.shared.global [%0], [%1], 16;"
                 :: "r"(sptr(dst)), "l"(src));
}
#define CP_COMMIT() asm volatile("cp.async.commit_group;" ::: "memory")
#define CP_WAIT1()  asm volatile("cp.async.wait_group 1;" ::: "memory")
#define CP_WAIT0()  asm volatile("cp.async.wait_group 0;" ::: "memory")

__device__ __forceinline__ unsigned pack_split2(float v0, float v1, unsigned& lo_out) {
    __nv_bfloat16 h0 = __float2bfloat16(v0), h1 = __float2bfloat16(v1);
    __nv_bfloat16 l0 = __float2bfloat16(v0 - __bfloat162float(h0));
    __nv_bfloat16 l1 = __float2bfloat16(v1 - __bfloat162float(h1));
    lo_out = (unsigned)__bfloat16_as_ushort(l0) | ((unsigned)__bfloat16_as_ushort(l1) << 16);
    return (unsigned)__bfloat16_as_ushort(h0) | ((unsigned)__bfloat16_as_ushort(h1) << 16);
}
__device__ __forceinline__ float bf2sum(unsigned hi, unsigned lo, int half) {
    unsigned short h = (unsigned short)(half ? (hi >> 16) : hi);
    unsigned short l = (unsigned short)(half ? (lo >> 16) : lo);
    return __bfloat162float(__ushort_as_bfloat16(h)) + __bfloat162float(__ushort_as_bfloat16(l));
}
__device__ __forceinline__ float ftanh(float x) {
    const float cx = fminf(fmaxf(x, -15.f), 15.f);
    const float e = __expf(2.f * cx);
    return __fdividef(e - 1.f, e + 1.f);
}

struct P {
    const __nv_bfloat16 *Ah, *Al, *Bh, *Bl, *B2h, *B2l;
    const float *Amask;                    // G3 for B2 mask
    const __nv_bfloat16 *Mh, *Ml;          // h2 planes for mask
    const __nv_bfloat16 *F3Ah, *F3Al, *F3Bh, *F3Bl;
    float *C, *C2;
    const float *cbias, *w1t, *bias, *b3, *E1;
    const __nv_bfloat16 *h1h, *h1l;
    __nv_bfloat16 *Oh, *Ol;
    float *y, *yacc, *ld, *psum;
    int stage;
    float t, cacc, cin, foldcoef;
};

// 128x64 CTA tile, 256 threads (8 warps: wm=wid&3, wn=wid>>2).
// MODE 0: by<8 G3 / by>=8 E1 (K=64, fp32 C)                  grid (32,16)
// MODE 1: by<8 F1 (K=64, tanh epi); by==8 fold rider          grid (32,9)
// MODE 2: F2 (K=512, tanh -> h2 planes)                       grid (32,8)
// MODE 3: by<8 B2 (K=512, masked A, logdet dot) / by==8 F3    grid (32,9)
template <int MODE>
__global__ void __launch_bounds__(256, 3) mma_k(P p) {
    extern __shared__ __align__(16) char dynsmem[];
    __nv_bfloat16* sAh = (__nv_bfloat16*)dynsmem;
    __nv_bfloat16* sAl = sAh + 2 * AT;
    __nv_bfloat16* sBh = sAl + 2 * AT;
    __nv_bfloat16* sBl = sBh + 2 * BT;
    float* red = (float*)(sBl + 2 * BT);

    const int tid = threadIdx.x, lane = tid & 31, wid = tid >> 5;
    const int wm = wid & 3, wn = wid >> 2;
    const int m0 = blockIdx.x * 128, by = blockIdx.y;

    if (MODE == 1 && by == 8) {   // fold rider
        if (p.foldcoef != 0.f && tid < 128) {
            const int m = m0 + tid;
            float s = 0.f;
            #pragma unroll
            for (int c = 0; c < 8; c++) s += p.psum[c * Bb + m];
            p.ld[m] += p.foldcoef * s;
        }
        return;
    }

    const bool isF3 = (MODE == 3 && by == 8);
    const bool maskA = (MODE == 3) && !isF3;

    const __nv_bfloat16 *Ah, *Al, *Bhp, *Blp;
    int lda, ldb, K, n0;
    float* C0 = nullptr;
    if (MODE == 0) {
        K = 64; lda = 64; ldb = 64;
        Ah = p.Ah; Al = p.Al;
        if (by < 8) { Bhp = p.Bh; Blp = p.Bl; C0 = p.C; n0 = by * 64; }
        else        { Bhp = p.B2h; Blp = p.B2l; C0 = p.C2; n0 = (by - 8) * 64; }
    } else if (MODE == 1) {
        K = 64; lda = 64; ldb = 64; n0 = by * 64;
        Ah = p.Ah; Al = p.Al; Bhp = p.Bh; Blp = p.Bl;
    } else if (MODE == 2) {
        K = 512; lda = 512; ldb = 512; n0 = by * 64;
        Ah = p.Ah; Al = p.Al; Bhp = p.Bh; Blp = p.Bl;
    } else if (!isF3) {
        K = 512; lda = 512; ldb = 512; n0 = by * 64;
        Ah = nullptr; Al = nullptr; Bhp = p.Bh; Blp = p.Bl;
    } else {
        K = 512; lda = 512; ldb = 512; n0 = 0;
        Ah = p.F3Ah; Al = p.F3Al; Bhp = p.F3Bh; Blp = p.F3Bl;
    }
    const int NT = K / 32;

    auto issue = [&](int kt) {
        const int buf = kt & 1;
        const int k0 = kt * 32;
        if (!maskA) {
            #pragma unroll
            for (int c = tid; c < 1024; c += 256) {
                const int plane = c >> 9, cc = c & 511;
                const int row = cc >> 2, ku = cc & 3;
                cp16((plane ? sAl : sAh) + buf * AT + row * SAS + ku * 8,
                     (plane ? Al : Ah) + (size_t)(m0 + row) * lda + k0 + ku * 8);
            }
        } else {
            #pragma unroll
            for (int c = tid; c < 512; c += 256) {
                const int row = c >> 2, ku = c & 3;
                const size_t go = (size_t)(m0 + row) * 512 + k0 + ku * 8;
                float g[8];
                *(float4*)(g)     = *(const float4*)(p.Amask + go);
                *(float4*)(g + 4) = *(const float4*)(p.Amask + go + 4);
                const uint4 mh4 = *(const uint4*)(p.Mh + go);
                const uint4 ml4 = *(const uint4*)(p.Ml + go);
                const __nv_bfloat16* mh = (const __nv_bfloat16*)&mh4;
                const __nv_bfloat16* ml = (const __nv_bfloat16*)&ml4;
                __nv_bfloat16 oh[8], ol[8];
                #pragma unroll
                for (int i = 0; i < 8; i++) {
                    const float h = __bfloat162float(mh[i]) + __bfloat162float(ml[i]);
                    const float v = g[i] * (1.f - h * h);
                    oh[i] = __float2bfloat16(v);
                    ol[i] = __float2bfloat16(v - __bfloat162float(oh[i]));
                }
                const int so = buf * AT + row * SAS + ku * 8;
                *(uint4*)&sAh[so] = *(const uint4*)oh;
                *(uint4*)&sAl[so] = *(const uint4*)ol;
            }
        }
        #pragma unroll
        for (int c = tid; c < 512; c += 256) {
            const int plane = c >> 8, cc = c & 255;
            const int row = cc >> 2, ku = cc & 3;
            cp16((plane ? sBl : sBh) + buf * BT + row * SAS + ku * 8,
                 (plane ? Blp : Bhp) + (size_t)(n0 + row) * ldb + k0 + ku * 8);
        }
        CP_COMMIT();
    };

    // fragment addressing
    const int l7 = lane & 7;
    const int aro = l7 + ((lane >> 3) & 1) * 8;
    const int aco = (lane >> 4) * 8;
    const int bro = l7 + (lane >> 4) * 8;
    const int bco = ((lane >> 3) & 1) * 8;

    float acc[2][4][4] = {};

    auto compute = [&](int buf) {
        const uint32_t bAh = sptr(sAh + buf * AT);
        const uint32_t bAl = sptr(sAl + buf * AT);
        const uint32_t bBh = sptr(sBh + buf * BT);
        const uint32_t bBl = sptr(sBl + buf * BT);
        #pragma unroll
        for (int kk = 0; kk < 2; kk++) {
            uint32_t ah[2][4], al[2][4], bh[2][4], bl[2][4];
            #pragma unroll
            for (int mt = 0; mt < 2; mt++) {
                const uint32_t off = ((wm * 32 + mt * 16 + aro) * SAS + kk * 16 + aco) * 2;
                ldm4(bAh + off, ah[mt][0], ah[mt][1], ah[mt][2], ah[mt][3]);
                ldm4(bAl + off, al[mt][0], al[mt][1], al[mt][2], al[mt][3]);
            }
            #pragma unroll
            for (int pn = 0; pn < 2; pn++) {
                const uint32_t off = ((wn * 32 + pn * 16 + bro) * SAS + kk * 16 + bco) * 2;
                ldm4(bBh + off, bh[pn][0], bh[pn][1], bh[pn][2], bh[pn][3]);
                ldm4(bBl + off, bl[pn][0], bl[pn][1], bl[pn][2], bl[pn][3]);
            }
            #pragma unroll
            for (int mt = 0; mt < 2; mt++)
                #pragma unroll
                for (int nt = 0; nt < 4; nt++) {
                    const uint32_t b0h = bh[nt >> 1][(nt & 1) * 2], b1h = bh[nt >> 1][(nt & 1) * 2 + 1];
                    const uint32_t b0l = bl[nt >> 1][(nt & 1) * 2], b1l = bl[nt >> 1][(nt & 1) * 2 + 1];
                    mma_bf16(acc[mt][nt], ah[mt], b0h, b1h);
                    mma_bf16(acc[mt][nt], ah[mt], b0l, b1l);
                    mma_bf16(acc[mt][nt], al[mt], b0h, b1h);
                }
        }
    };

    issue(0);
    for (int kt = 0; kt < NT; kt++) {
        if (kt + 1 < NT) { issue(kt + 1); CP_WAIT1(); } else { CP_WAIT0(); }
        __syncthreads();
        compute(kt & 1);
        __syncthreads();
    }

    // ---- epilogues ----
    const int g = lane >> 2, tt = lane & 3;

    if (MODE == 3 && !isF3) {   // B2 logdet dot
        float s[4] = {0.f, 0.f, 0.f, 0.f};
        #pragma unroll
        for (int mt = 0; mt < 2; mt++)
            #pragma unroll
            for (int nt = 0; nt < 4; nt++) {
                const int c = n0 + wn * 32 + nt * 8 + tt * 2;
                #pragma unroll
                for (int hr = 0; hr < 2; hr++) {
                    const int r = m0 + wm * 32 + mt * 16 + g + hr * 8;
                    const size_t off = (size_t)r * 512 + c;
                    const unsigned hh = *(const unsigned*)&p.h1h[off];
                    const unsigned hl = *(const unsigned*)&p.h1l[off];
                    const float2 e = *(const float2*)&p.E1[off];
                    const float h0 = bf2sum(hh, hl, 0), h1v = bf2sum(hh, hl, 1);
                    s[mt * 2 + hr] += acc[mt][nt][hr * 2 + 0] * (1.f - h0 * h0) * e.x
                                    + acc[mt][nt][hr * 2 + 1] * (1.f - h1v * h1v) * e.y;
                }
            }
        #pragma unroll
        for (int i = 0; i < 4; i++) {
            s[i] += __shfl_xor_sync(0xffffffffu, s[i], 1);
            s[i] += __shfl_xor_sync(0xffffffffu, s[i], 2);
        }
        if (tt == 0) {
            #pragma unroll
            for (int mt = 0; mt < 2; mt++)
                #pragma unroll
                for (int hr = 0; hr < 2; hr++)
                    red[(wm * 32 + mt * 16 + g + hr * 8) * 2 + wn] = s[mt * 2 + hr];
        }
        __syncthreads();
        if (tid < 128)
            p.psum[(size_t)by * Bb + m0 + tid] = red[tid * 2] + red[tid * 2 + 1];
        return;
    }

    if (isF3) {   // F3 + RK4
        unsigned* yinhU = (unsigned*)p.Oh;
        unsigned* yinlU = (unsigned*)p.Ol;
        #pragma unroll
        for (int mt = 0; mt < 2; mt++)
            #pragma unroll
            for (int nt = 0; nt < 4; nt++) {
                const int c = wn * 32 + nt * 8 + tt * 2;
                const float2 b3v = *(const float2*)&p.b3[c];
                #pragma unroll
                for (int hr = 0; hr < 2; hr++) {
                    const int r = m0 + wm * 32 + mt * 16 + g + hr * 8;
                    const size_t idx = (size_t)r * 64 + c;
                    const float kv0 = acc[mt][nt][hr * 2 + 0] + b3v.x;
                    const float kv1 = acc[mt][nt][hr * 2 + 1] + b3v.y;
                    const float2 base = (p.stage == 1) ? *(const float2*)&p.y[idx]
                                                       : *(const float2*)&p.yacc[idx];
                    const float ya0 = base.x + p.cacc * kv0;
                    const float ya1 = base.y + p.cacc * kv1;
                    float yi0, yi1;
                    if (p.stage == 4) {
                        *(float2*)&p.y[idx] = make_float2(ya0, ya1);
                        yi0 = ya0; yi1 = ya1;
                    } else {
                        *(float2*)&p.yacc[idx] = make_float2(ya0, ya1);
                        const float2 yv = *(const float2*)&p.y[idx];
                        yi0 = yv.x + p.cin * kv0;
                        yi1 = yv.y + p.cin * kv1;
                    }
                    unsigned lo, hi = pack_split2(yi0, yi1, lo);
                    yinhU[idx >> 1] = hi;
                    yinlU[idx >> 1] = lo;
                }
            }
        return;
    }

    // MODE 0/1/2 fragment epilogues
    #pragma unroll
    for (int mt = 0; mt < 2; mt++)
        #pragma unroll
        for (int nt = 0; nt < 4; nt++) {
            const int c = n0 + wn * 32 + nt * 8 + tt * 2;
            #pragma unroll
            for (int hr = 0; hr < 2; hr++) {
                const int r = m0 + wm * 32 + mt * 16 + g + hr * 8;
                float v0 = acc[mt][nt][hr * 2 + 0];
                float v1 = acc[mt][nt][hr * 2 + 1];
                const size_t off = (size_t)r * 512 + c;
                if (MODE == 0) {
                    *(float2*)&C0[off] = make_float2(v0, v1);
                } else if (MODE == 1) {
                    const float2 cb = *(const float2*)&p.cbias[off];
                    const float2 wt = *(const float2*)&p.w1t[c];
                    v0 = ftanh(v0 + cb.x + p.t * wt.x);
                    v1 = ftanh(v1 + cb.y + p.t * wt.y);
                    unsigned lo, hi = pack_split2(v0, v1, lo);
                    ((unsigned*)p.Oh)[off >> 1] = hi;
                    ((unsigned*)p.Ol)[off >> 1] = lo;
                } else {
                    const float2 bi = *(const float2*)&p.bias[c];
                    v0 = ftanh(v0 + bi.x);
                    v1 = ftanh(v1 + bi.y);
                    unsigned lo, hi = pack_split2(v0, v1, lo);
                    ((unsigned*)p.Oh)[off >> 1] = hi;
                    ((unsigned*)p.Ol)[off >> 1] = lo;
                }
            }
        }
}

// ---------------- aux kernels ----------------
__device__ __forceinline__ void wsplit(float v, __nv_bfloat16* h, __nv_bfloat16* l, size_t i) {
    const __nv_bfloat16 hv = __float2bfloat16(v);
    h[i] = hv;
    l[i] = __float2bfloat16(v - __bfloat162float(hv));
}
__global__ void prep_k(const float* __restrict__ eps, const float* __restrict__ W2,
                       const float* __restrict__ W3, const float* __restrict__ W1,
                       __nv_bfloat16* eph, __nv_bfloat16* epl,
                       __nv_bfloat16* w2h, __nv_bfloat16* w2l,
                       __nv_bfloat16* w3h, __nv_bfloat16* w3l,
                       __nv_bfloat16* w2th, __nv_bfloat16* w2tl,
                       __nv_bfloat16* w1yth, __nv_bfloat16* w1ytl,
                       __nv_bfloat16* w3th, __nv_bfloat16* w3tl) {
    int i = blockIdx.x * 256 + threadIdx.x;
    if (i < Bb * Dd) { wsplit(eps[i], eph, epl, i); return; }
    i -= Bb * Dd;
    if (i < Hh * Hh) { wsplit(W2[i], w2h, w2l, i); return; }
    i -= Hh * Hh;
    if (i < Hh * Dd) { wsplit(W3[i], w3h, w3l, i); return; }
    i -= Hh * Dd;
    if (i < Hh * Hh) {
        const int r = i / Hh, c = i % Hh;
        wsplit(W2[i], w2th, w2tl, (size_t)c * Hh + r);
        return;
    }
    i -= Hh * Hh;
    if (i < Dd * Hh) {
        const int r = i / Hh, c = i % Hh;
        wsplit(W1[i], w1yth, w1ytl, (size_t)c * Dd + r);
        return;
    }
    i -= Dd * Hh;
    if (i < Hh * Dd) {
        const int r = i / Dd, c = i % Dd;   // W3[r][c], r in [0,512), c in [0,64)
        wsplit(W3[i], w3th, w3tl, (size_t)c * Hh + r);
    }
}
__global__ void cbias_k(const float* __restrict__ cond, const float* __restrict__ W1c,
                        const float* __restrict__ b1, float* __restrict__ cb) {
    const int m = blockIdx.x;
    const int n = threadIdx.x * 4;
    float4 acc = *(const float4*)(b1 + n);
    #pragma unroll
    for (int k = 0; k < Cc; k++) {
        const float c = cond[m * Cc + k];
        const float4 w = *(const float4*)(W1c + (size_t)k * Hh + n);
        acc.x = fmaf(c, w.x, acc.x); acc.y = fmaf(c, w.y, acc.y);
        acc.z = fmaf(c, w.z, acc.z); acc.w = fmaf(c, w.w, acc.w);
    }
    *(float4*)(cb + (size_t)m * Hh + n) = acc;
}
__global__ void init_k(const float* __restrict__ x, float* __restrict__ y,
                       __nv_bfloat16* __restrict__ yinh, __nv_bfloat16* __restrict__ yinl,
                       float* __restrict__ ld) {
    const int i = blockIdx.x * blockDim.x + threadIdx.x;
    if (i < Bb * Dd) {
        const float v = x[i];
        y[i] = v;
        wsplit(v, yinh, yinl, i);
    }
    if (i < Bb) ld[i] = 0.f;
}
__global__ void out_k(const float* __restrict__ y, const float* __restrict__ ld,
                      const float* __restrict__ psum, float coef, float* __restrict__ out) {
    const int i = blockIdx.x * blockDim.x + threadIdx.x;
    if (i >= Bb * (Dd + 1)) return;
    const int m = i / (Dd + 1), c = i % (Dd + 1);
    if (c < Dd) {
        out[i] = y[(size_t)m * Dd + c];
    } else {
        float s = 0.f;
        #pragma unroll
        for (int c2 = 0; c2 < 8; c2++) s += psum[c2 * Bb + m];
        out[i] = ld[m] + coef * s;
    }
}

// ---------------- host ----------------
extern "C" void kernel_launch(void* const* d_in, const int* in_sizes, int n_in,
                              void* d_out, int out_size) {
    const float* x    = (const float*)d_in[0];
    const float* cond = (const float*)d_in[1];
    const float* eps  = (const float*)d_in[2];
    const float* W1   = (const float*)d_in[3];
    const float* b1   = (const float*)d_in[4];
    const float* W2   = (const float*)d_in[5];
    const float* b2   = (const float*)d_in[6];
    const float* W3   = (const float*)d_in[7];
    const float* b3   = (const float*)d_in[8];
    float* out = (float*)d_out;

    cudaFuncSetAttribute(mma_k<0>, cudaFuncAttributeMaxDynamicSharedMemorySize, SMEM_BYTES);
    cudaFuncSetAttribute(mma_k<1>, cudaFuncAttributeMaxDynamicSharedMemorySize, SMEM_BYTES);
    cudaFuncSetAttribute(mma_k<2>, cudaFuncAttributeMaxDynamicSharedMemorySize, SMEM_BYTES);
    cudaFuncSetAttribute(mma_k<3>, cudaFuncAttributeMaxDynamicSharedMemorySize, SMEM_BYTES);

    #define SYM(T, v, s) T* v; { void* _p; cudaGetSymbolAddress(&_p, s); v = (T*)_p; }
    SYM(float, y, g_y) SYM(float, yacc, g_yacc) SYM(float, cb, g_cb)
    SYM(float, G3, g_G3) SYM(float, E1, g_E1) SYM(float, ld, g_ld) SYM(float, psum, g_psum)
    SYM(__nv_bfloat16, h1h, g_h1h) SYM(__nv_bfloat16, h1l, g_h1l)
    SYM(__nv_bfloat16, h2h, g_h2h) SYM(__nv_bfloat16, h2l, g_h2l)
    SYM(__nv_bfloat16, yinh, g_yinh) SYM(__nv_bfloat16, yinl, g_yinl)
    SYM(__nv_bfloat16, epsh, g_epsh) SYM(__nv_bfloat16, epsl, g_epsl)
    SYM(__nv_bfloat16, W2h, g_W2h) SYM(__nv_bfloat16, W2l, g_W2l)
    SYM(__nv_bfloat16, W2Th, g_W2Th) SYM(__nv_bfloat16, W2Tl, g_W2Tl)
    SYM(__nv_bfloat16, W3h, g_W3h) SYM(__nv_bfloat16, W3l, g_W3l)
    SYM(__nv_bfloat16, W3Th, g_W3Th) SYM(__nv_bfloat16, W3Tl, g_W3Tl)
    SYM(__nv_bfloat16, W1yTh, g_W1yTh) SYM(__nv_bfloat16, W1yTl, g_W1yTl)
    #undef SYM

    init_k<<<(Bb * Dd + 255) / 256, 256>>>(x, y, yinh, yinl, ld);

    constexpr int PREP_N = Bb * Dd + Hh * Hh + Hh * Dd + Hh * Hh + Dd * Hh + Hh * Dd;
    const float dt = 1.0f / NS;
    float prev_cl = 0.f;

    for (int ib = 0; ib < NB; ib++) {
        const float* W1b  = W1 + (size_t)ib * (Dd + Cc + 1) * Hh;
        const float* b1b  = b1 + (size_t)ib * Hh;
        const float* W2b  = W2 + (size_t)ib * Hh * Hh;
        const float* b2b  = b2 + (size_t)ib * Hh;
        const float* W3b  = W3 + (size_t)ib * Hh * Dd;
        const float* b3b  = b3 + (size_t)ib * Dd;
        const float* epsb = eps + (size_t)ib * Bb * Dd;
        float* cbb = cb + (size_t)ib * Bb * Hh;
        float* G3b = G3 + (size_t)ib * Bb * Hh;
        float* E1b = E1 + (size_t)ib * Bb * Hh;
        __nv_bfloat16 *eph = epsh + (size_t)ib * Bb * Dd, *epl = epsl + (size_t)ib * Bb * Dd;
        __nv_bfloat16 *w2h = W2h + (size_t)ib * Hh * Hh, *w2l = W2l + (size_t)ib * Hh * Hh;
        __nv_bfloat16 *w2th = W2Th + (size_t)ib * Hh * Hh, *w2tl = W2Tl + (size_t)ib * Hh * Hh;
        __nv_bfloat16 *w3h = W3h + (size_t)ib * Hh * Dd, *w3l = W3l + (size_t)ib * Hh * Dd;
        __nv_bfloat16 *w3th = W3Th + (size_t)ib * Dd * Hh, *w3tl = W3Tl + (size_t)ib * Dd * Hh;
        __nv_bfloat16 *w1yth = W1yTh + (size_t)ib * Hh * Dd, *w1ytl = W1yTl + (size_t)ib * Hh * Dd;

        prep_k<<<(PREP_N + 255) / 256, 256>>>(epsb, W2b, W3b, W1b,
            eph, epl, w2h, w2l, w3h, w3l, w2th, w2tl, w1yth, w1ytl, w3th, w3tl);
        cbias_k<<<Bb, 128>>>(cond, W1b + (size_t)Dd * Hh, b1b, cbb);

        {   // merged G3 (by<8) + E1 (by>=8)
            P p{}; p.Ah = eph; p.Al = epl;
            p.Bh = w3h; p.Bl = w3l; p.C = G3b;
            p.B2h = w1yth; p.B2l = w1ytl; p.C2 = E1b;
            mma_k<0><<<dim3(32, 16), 256, SMEM_BYTES>>>(p);
        }

        for (int is = 0; is < NS; is++) {
            const float tbase = is * dt;
            for (int st = 1; st <= 4; st++) {
                const float t = tbase + (st == 1 ? 0.f : (st == 4 ? dt : 0.5f * dt));
                const float cacc = (st == 1 || st == 4) ? dt / 6.f : dt / 3.f;
                const float cin  = (st == 3) ? dt : 0.5f * dt;

                {   // F1 + fold rider
                    P p{}; p.Ah = yinh; p.Al = yinl; p.Bh = w1yth; p.Bl = w1ytl;
                    p.cbias = cbb; p.w1t = W1b + (size_t)(Dd + Cc) * Hh; p.t = t;
                    p.Oh = h1h; p.Ol = h1l;
                    p.foldcoef = prev_cl; p.ld = ld; p.psum = psum;
                    mma_k<1><<<dim3(32, 9), 256, SMEM_BYTES>>>(p);
                }
                {   // F2
                    P p{}; p.Ah = h1h; p.Al = h1l; p.Bh = w2th; p.Bl = w2tl;
                    p.bias = b2b; p.Oh = h2h; p.Ol = h2l;
                    mma_k<2><<<dim3(32, 8), 256, SMEM_BYTES>>>(p);
                }
                {   // FUSED: B2 + logdet dot (by<8), F3 + RK4 (by==8)
                    P p{};
                    p.Amask = G3b; p.Mh = h2h; p.Ml = h2l;
                    p.Bh = w2h; p.Bl = w2l;
                    p.F3Ah = h2h; p.F3Al = h2l; p.F3Bh = w3th; p.F3Bl = w3tl;
                    p.h1h = h1h; p.h1l = h1l; p.E1 = E1b; p.psum = psum;
                    p.b3 = b3b; p.y = y; p.yacc = yacc; p.Oh = yinh; p.Ol = yinl;
                    p.stage = st; p.cacc = cacc; p.cin = cin;
                    mma_k<3><<<dim3(32, 9), 256, SMEM_BYTES>>>(p);
                }
                prev_cl = cacc;
            }
        }
    }

    out_k<<<(Bb * (Dd + 1) + 255) / 256, 256>>>(y, ld, psum, prev_cl, out);
}

// round 9
// speedup vs baseline: 1.3394x; 1.0814x over previous
#include <cuda_runtime.h>
#include <cuda_bf16.h>
#include <cuda_fp16.h>
#include <math.h>
#include <stdint.h>

namespace {
constexpr int Bb = 4096, Dd = 64, Cc = 16, Hh = 512, NB = 2, NS = 8;
constexpr int SAS = 40;               // smem row stride in halves (80B)
constexpr int AT = 128 * SAS;         // A halves per buffer
constexpr int BT = 64 * SAS;          // B halves per buffer
constexpr int SMEM_BYTES = (2 * AT + 2 * AT + 2 * BT + 2 * BT) * 2 + 256 * 4;
}

// ---------------- device scratch ----------------
__device__ __align__(16) __nv_bfloat16 g_h1h[Bb * Hh], g_h1l[Bb * Hh];
__device__ __align__(16) __nv_bfloat16 g_h2h[Bb * Hh], g_h2l[Bb * Hh];
__device__ __align__(16) __nv_bfloat16 g_yinh[Bb * Dd], g_yinl[Bb * Dd];
__device__ __align__(16) float g_y[Bb * Dd], g_yacc[Bb * Dd];
__device__ __align__(16) float g_cb[NB * Bb * Hh], g_G3[NB * Bb * Hh], g_E1[NB * Bb * Hh];
__device__ __align__(16) float g_ld[Bb], g_psum[8 * Bb];
__device__ __align__(16) __nv_bfloat16 g_epsh[NB * Bb * Dd],  g_epsl[NB * Bb * Dd];
__device__ __align__(16) __half        g_W2f [NB * Hh * Hh];                            // [n][k] fp16, B2
__device__ __align__(16) __nv_bfloat16 g_W2Th[NB * Hh * Hh],  g_W2Tl[NB * Hh * Hh];   // [n][k] F2
__device__ __align__(16) __nv_bfloat16 g_W3h [NB * Hh * Dd],  g_W3l [NB * Hh * Dd];   // [512][64] G3
__device__ __align__(16) __nv_bfloat16 g_W3Th[NB * Dd * Hh],  g_W3Tl[NB * Dd * Hh];   // [64][512] F3
__device__ __align__(16) __nv_bfloat16 g_W1yTh[NB * Hh * Dd], g_W1yTl[NB * Hh * Dd];  // [512][64] F1/E1

// ---------------- helpers ----------------
__device__ __forceinline__ uint32_t sptr(const void* p) {
    return (uint32_t)__cvta_generic_to_shared(p);
}
__device__ __forceinline__ void ldm4(uint32_t a, uint32_t& r0, uint32_t& r1,
                                     uint32_t& r2, uint32_t& r3) {
    asm volatile("ldmatrix.sync.aligned.m8n8.x4.shared.b16 {%0,%1,%2,%3}, [%4];"
                 : "=r"(r0), "=r"(r1), "=r"(r2), "=r"(r3) : "r"(a));
}
__device__ __forceinline__ void mma_bf16(float* c, const uint32_t* a, uint32_t b0, uint32_t b1) {
    asm volatile("mma.sync.aligned.m16n8k16.row.col.f32.bf16.bf16.f32 "
                 "{%0,%1,%2,%3}, {%4,%5,%6,%7}, {%8,%9}, {%0,%1,%2,%3};"
                 : "+f"(c[0]), "+f"(c[1]), "+f"(c[2]), "+f"(c[3])
                 : "r"(a[0]), "r"(a[1]), "r"(a[2]), "r"(a[3]), "r"(b0), "r"(b1));
}
__device__ __forceinline__ void mma_f16(float* c, const uint32_t* a, uint32_t b0, uint32_t b1) {
    asm volatile("mma.sync.aligned.m16n8k16.row.col.f32.f16.f16.f32 "
                 "{%0,%1,%2,%3}, {%4,%5,%6,%7}, {%8,%9}, {%0,%1,%2,%3};"
                 : "+f"(c[0]), "+f"(c[1]), "+f"(c[2]), "+f"(c[3])
                 : "r"(a[0]), "r"(a[1]), "r"(a[2]), "r"(a[3]), "r"(b0), "r"(b1));
}
__device__ __forceinline__ void cp16(void* dst, const void* src) {
    asm volatile("cp.async.cg.shared.global [%0], [%1], 16;"
                 :: "r"(sptr(dst)), "l"(src));
}
#define CP_COMMIT() asm volatile("cp.async.commit_group;" ::: "memory")
#define CP_WAIT1()  asm volatile("cp.async.wait_group 1;" ::: "memory")
#define CP_WAIT0()  asm volatile("cp.async.wait_group 0;" ::: "memory")

__device__ __forceinline__ unsigned pack_split2(float v0, float v1, unsigned& lo_out) {
    __nv_bfloat16 h0 = __float2bfloat16(v0), h1 = __float2bfloat16(v1);
    __nv_bfloat16 l0 = __float2bfloat16(v0 - __bfloat162float(h0));
    __nv_bfloat16 l1 = __float2bfloat16(v1 - __bfloat162float(h1));
    lo_out = (unsigned)__bfloat16_as_ushort(l0) | ((unsigned)__bfloat16_as_ushort(l1) << 16);
    return (unsigned)__bfloat16_as_ushort(h0) | ((unsigned)__bfloat16_as_ushort(h1) << 16);
}
__device__ __forceinline__ float bf2sum(unsigned hi, unsigned lo, int half) {
    unsigned short h = (unsigned short)(half ? (hi >> 16) : hi);
    unsigned short l = (unsigned short)(half ? (lo >> 16) : lo);
    return __bfloat162float(__ushort_as_bfloat16(h)) + __bfloat162float(__ushort_as_bfloat16(l));
}
__device__ __forceinline__ float ftanh(float x) {
    const float cx = fminf(fmaxf(x, -15.f), 15.f);
    const float e = __expf(2.f * cx);
    return __fdividef(e - 1.f, e + 1.f);
}

struct P {
    const __nv_bfloat16 *Ah, *Al, *Bh, *Bl, *B2h, *B2l;
    const float *Amask;                    // G3 for B2 mask
    const __nv_bfloat16 *Mh, *Ml;          // h2 planes for mask
    const __half *W2f;                     // fp16 W2 [n][k] for B2
    const __nv_bfloat16 *F3Ah, *F3Al, *F3Bh, *F3Bl;
    float *C, *C2;
    const float *cbias, *w1t, *bias, *b3, *E1;
    const __nv_bfloat16 *h1h, *h1l;
    __nv_bfloat16 *Oh, *Ol;
    float *y, *yacc, *ld, *psum;
    int stage;
    float t, cacc, cin, foldcoef;
};

// 128x64 CTA tile, 256 threads (8 warps: wm=wid&3, wn=wid>>2).
// MODE 0: by<8 G3 / by>=8 E1 (K=64, fp32 C)                           grid (32,16)
// MODE 1: by<8 F1 (K=64, tanh epi); by==8 fold rider                   grid (32,9)
// MODE 2: F2 (K=512, tanh -> h2 planes)                                grid (32,8)
// MODE 3: by<8 B2 (K=512, SINGLE fp16: masked A, logdet dot) / by==8 F3 (3-term bf16)  grid (32,9)
template <int MODE>
__global__ void __launch_bounds__(256, 3) mma_k(P p) {
    extern __shared__ __align__(16) char dynsmem[];
    __nv_bfloat16* sAh = (__nv_bfloat16*)dynsmem;
    __nv_bfloat16* sAl = sAh + 2 * AT;
    __nv_bfloat16* sBh = sAl + 2 * AT;
    __nv_bfloat16* sBl = sBh + 2 * BT;
    float* red = (float*)(sBl + 2 * BT);

    const int tid = threadIdx.x, lane = tid & 31, wid = tid >> 5;
    const int wm = wid & 3, wn = wid >> 2;
    const int m0 = blockIdx.x * 128, by = blockIdx.y;

    if (MODE == 1 && by == 8) {   // fold rider
        if (p.foldcoef != 0.f && tid < 128) {
            const int m = m0 + tid;
            float s = 0.f;
            #pragma unroll
            for (int c = 0; c < 8; c++) s += p.psum[c * Bb + m];
            p.ld[m] += p.foldcoef * s;
        }
        return;
    }

    const bool isF3 = (MODE == 3 && by == 8);
    const bool maskA = (MODE == 3) && !isF3;   // single-fp16 B2 path

    const __nv_bfloat16 *Ah, *Al, *Bhp, *Blp;
    int lda, ldb, K, n0;
    float* C0 = nullptr;
    if (MODE == 0) {
        K = 64; lda = 64; ldb = 64;
        Ah = p.Ah; Al = p.Al;
        if (by < 8) { Bhp = p.Bh; Blp = p.Bl; C0 = p.C; n0 = by * 64; }
        else        { Bhp = p.B2h; Blp = p.B2l; C0 = p.C2; n0 = (by - 8) * 64; }
    } else if (MODE == 1) {
        K = 64; lda = 64; ldb = 64; n0 = by * 64;
        Ah = p.Ah; Al = p.Al; Bhp = p.Bh; Blp = p.Bl;
    } else if (MODE == 2) {
        K = 512; lda = 512; ldb = 512; n0 = by * 64;
        Ah = p.Ah; Al = p.Al; Bhp = p.Bh; Blp = p.Bl;
    } else if (!isF3) {
        K = 512; lda = 512; ldb = 512; n0 = by * 64;
        Ah = nullptr; Al = nullptr; Bhp = nullptr; Blp = nullptr;
    } else {
        K = 512; lda = 512; ldb = 512; n0 = 0;
        Ah = p.F3Ah; Al = p.F3Al; Bhp = p.F3Bh; Blp = p.F3Bl;
    }
    const int NT = K / 32;

    auto issue = [&](int kt) {
        const int buf = kt & 1;
        const int k0 = kt * 32;
        if (!maskA) {
            #pragma unroll
            for (int c = tid; c < 1024; c += 256) {
                const int plane = c >> 9, cc = c & 511;
                const int row = cc >> 2, ku = cc & 3;
                cp16((plane ? sAl : sAh) + buf * AT + row * SAS + ku * 8,
                     (plane ? Al : Ah) + (size_t)(m0 + row) * lda + k0 + ku * 8);
            }
            #pragma unroll
            for (int c = tid; c < 512; c += 256) {
                const int plane = c >> 8, cc = c & 255;
                const int row = cc >> 2, ku = cc & 3;
                cp16((plane ? sBl : sBh) + buf * BT + row * SAS + ku * 8,
                     (plane ? Blp : Bhp) + (size_t)(n0 + row) * ldb + k0 + ku * 8);
            }
        } else {
            // single fp16 plane: A = G3*(1-h2^2), B = W2 fp16
            #pragma unroll
            for (int c = tid; c < 512; c += 256) {
                const int row = c >> 2, ku = c & 3;
                const size_t go = (size_t)(m0 + row) * 512 + k0 + ku * 8;
                float g[8];
                *(float4*)(g)     = *(const float4*)(p.Amask + go);
                *(float4*)(g + 4) = *(const float4*)(p.Amask + go + 4);
                const uint4 mh4 = *(const uint4*)(p.Mh + go);
                const uint4 ml4 = *(const uint4*)(p.Ml + go);
                const __nv_bfloat16* mh = (const __nv_bfloat16*)&mh4;
                const __nv_bfloat16* ml = (const __nv_bfloat16*)&ml4;
                __half hv[8];
                #pragma unroll
                for (int i = 0; i < 8; i++) {
                    const float h = __bfloat162float(mh[i]) + __bfloat162float(ml[i]);
                    hv[i] = __float2half_rn(g[i] * (1.f - h * h));
                }
                const int so = buf * AT + row * SAS + ku * 8;
                *(uint4*)&sAh[so] = *(const uint4*)hv;
            }
            {
                const int c = tid;   // 256 chunks, one per thread
                const int row = c >> 2, ku = c & 3;
                cp16(sBh + buf * BT + row * SAS + ku * 8,
                     p.W2f + (size_t)(n0 + row) * 512 + k0 + ku * 8);
            }
        }
        CP_COMMIT();
    };

    // fragment addressing
    const int l7 = lane & 7;
    const int aro = l7 + ((lane >> 3) & 1) * 8;
    const int aco = (lane >> 4) * 8;
    const int bro = l7 + (lane >> 4) * 8;
    const int bco = ((lane >> 3) & 1) * 8;

    float acc[2][4][4] = {};

    auto compute = [&](int buf) {
        const uint32_t bAh = sptr(sAh + buf * AT);
        const uint32_t bAl = sptr(sAl + buf * AT);
        const uint32_t bBh = sptr(sBh + buf * BT);
        const uint32_t bBl = sptr(sBl + buf * BT);
        if (maskA) {   // single fp16 MMA path
            #pragma unroll
            for (int kk = 0; kk < 2; kk++) {
                uint32_t ah[2][4], bh[2][4];
                #pragma unroll
                for (int mt = 0; mt < 2; mt++) {
                    const uint32_t off = ((wm * 32 + mt * 16 + aro) * SAS + kk * 16 + aco) * 2;
                    ldm4(bAh + off, ah[mt][0], ah[mt][1], ah[mt][2], ah[mt][3]);
                }
                #pragma unroll
                for (int pn = 0; pn < 2; pn++) {
                    const uint32_t off = ((wn * 32 + pn * 16 + bro) * SAS + kk * 16 + bco) * 2;
                    ldm4(bBh + off, bh[pn][0], bh[pn][1], bh[pn][2], bh[pn][3]);
                }
                #pragma unroll
                for (int mt = 0; mt < 2; mt++)
                    #pragma unroll
                    for (int nt = 0; nt < 4; nt++)
                        mma_f16(acc[mt][nt], ah[mt],
                                bh[nt >> 1][(nt & 1) * 2], bh[nt >> 1][(nt & 1) * 2 + 1]);
            }
            return;
        }
        #pragma unroll
        for (int kk = 0; kk < 2; kk++) {
            uint32_t ah[2][4], al[2][4], bh[2][4], bl[2][4];
            #pragma unroll
            for (int mt = 0; mt < 2; mt++) {
                const uint32_t off = ((wm * 32 + mt * 16 + aro) * SAS + kk * 16 + aco) * 2;
                ldm4(bAh + off, ah[mt][0], ah[mt][1], ah[mt][2], ah[mt][3]);
                ldm4(bAl + off, al[mt][0], al[mt][1], al[mt][2], al[mt][3]);
            }
            #pragma unroll
            for (int pn = 0; pn < 2; pn++) {
                const uint32_t off = ((wn * 32 + pn * 16 + bro) * SAS + kk * 16 + bco) * 2;
                ldm4(bBh + off, bh[pn][0], bh[pn][1], bh[pn][2], bh[pn][3]);
                ldm4(bBl + off, bl[pn][0], bl[pn][1], bl[pn][2], bl[pn][3]);
            }
            #pragma unroll
            for (int mt = 0; mt < 2; mt++)
                #pragma unroll
                for (int nt = 0; nt < 4; nt++) {
                    const uint32_t b0h = bh[nt >> 1][(nt & 1) * 2], b1h = bh[nt >> 1][(nt & 1) * 2 + 1];
                    const uint32_t b0l = bl[nt >> 1][(nt & 1) * 2], b1l = bl[nt >> 1][(nt & 1) * 2 + 1];
                    mma_bf16(acc[mt][nt], ah[mt], b0h, b1h);
                    mma_bf16(acc[mt][nt], ah[mt], b0l, b1l);
                    mma_bf16(acc[mt][nt], al[mt], b0h, b1h);
                }
        }
    };

    issue(0);
    for (int kt = 0; kt < NT; kt++) {
        if (kt + 1 < NT) { issue(kt + 1); CP_WAIT1(); } else { CP_WAIT0(); }
        __syncthreads();
        compute(kt & 1);
        __syncthreads();
    }

    // ---- epilogues ----
    const int g = lane >> 2, tt = lane & 3;

    if (MODE == 3 && !isF3) {   // B2 logdet dot
        float s[4] = {0.f, 0.f, 0.f, 0.f};
        #pragma unroll
        for (int mt = 0; mt < 2; mt++)
            #pragma unroll
            for (int nt = 0; nt < 4; nt++) {
                const int c = n0 + wn * 32 + nt * 8 + tt * 2;
                #pragma unroll
                for (int hr = 0; hr < 2; hr++) {
                    const int r = m0 + wm * 32 + mt * 16 + g + hr * 8;
                    const size_t off = (size_t)r * 512 + c;
                    const unsigned hh = *(const unsigned*)&p.h1h[off];
                    const unsigned hl = *(const unsigned*)&p.h1l[off];
                    const float2 e = *(const float2*)&p.E1[off];
                    const float h0 = bf2sum(hh, hl, 0), h1v = bf2sum(hh, hl, 1);
                    s[mt * 2 + hr] += acc[mt][nt][hr * 2 + 0] * (1.f - h0 * h0) * e.x
                                    + acc[mt][nt][hr * 2 + 1] * (1.f - h1v * h1v) * e.y;
                }
            }
        #pragma unroll
        for (int i = 0; i < 4; i++) {
            s[i] += __shfl_xor_sync(0xffffffffu, s[i], 1);
            s[i] += __shfl_xor_sync(0xffffffffu, s[i], 2);
        }
        if (tt == 0) {
            #pragma unroll
            for (int mt = 0; mt < 2; mt++)
                #pragma unroll
                for (int hr = 0; hr < 2; hr++)
                    red[(wm * 32 + mt * 16 + g + hr * 8) * 2 + wn] = s[mt * 2 + hr];
        }
        __syncthreads();
        if (tid < 128)
            p.psum[(size_t)by * Bb + m0 + tid] = red[tid * 2] + red[tid * 2 + 1];
        return;
    }

    if (isF3) {   // F3 + RK4
        unsigned* yinhU = (unsigned*)p.Oh;
        unsigned* yinlU = (unsigned*)p.Ol;
        #pragma unroll
        for (int mt = 0; mt < 2; mt++)
            #pragma unroll
            for (int nt = 0; nt < 4; nt++) {
                const int c = wn * 32 + nt * 8 + tt * 2;
                const float2 b3v = *(const float2*)&p.b3[c];
                #pragma unroll
                for (int hr = 0; hr < 2; hr++) {
                    const int r = m0 + wm * 32 + mt * 16 + g + hr * 8;
                    const size_t idx = (size_t)r * 64 + c;
                    const float kv0 = acc[mt][nt][hr * 2 + 0] + b3v.x;
                    const float kv1 = acc[mt][nt][hr * 2 + 1] + b3v.y;
                    const float2 base = (p.stage == 1) ? *(const float2*)&p.y[idx]
                                                       : *(const float2*)&p.yacc[idx];
                    const float ya0 = base.x + p.cacc * kv0;
                    const float ya1 = base.y + p.cacc * kv1;
                    float yi0, yi1;
                    if (p.stage == 4) {
                        *(float2*)&p.y[idx] = make_float2(ya0, ya1);
                        yi0 = ya0; yi1 = ya1;
                    } else {
                        *(float2*)&p.yacc[idx] = make_float2(ya0, ya1);
                        const float2 yv = *(const float2*)&p.y[idx];
                        yi0 = yv.x + p.cin * kv0;
                        yi1 = yv.y + p.cin * kv1;
                    }
                    unsigned lo, hi = pack_split2(yi0, yi1, lo);
                    yinhU[idx >> 1] = hi;
                    yinlU[idx >> 1] = lo;
                }
            }
        return;
    }

    // MODE 0/1/2 fragment epilogues
    #pragma unroll
    for (int mt = 0; mt < 2; mt++)
        #pragma unroll
        for (int nt = 0; nt < 4; nt++) {
            const int c = n0 + wn * 32 + nt * 8 + tt * 2;
            #pragma unroll
            for (int hr = 0; hr < 2; hr++) {
                const int r = m0 + wm * 32 + mt * 16 + g + hr * 8;
                float v0 = acc[mt][nt][hr * 2 + 0];
                float v1 = acc[mt][nt][hr * 2 + 1];
                const size_t off = (size_t)r * 512 + c;
                if (MODE == 0) {
                    *(float2*)&C0[off] = make_float2(v0, v1);
                } else if (MODE == 1) {
                    const float2 cb = *(const float2*)&p.cbias[off];
                    const float2 wt = *(const float2*)&p.w1t[c];
                    v0 = ftanh(v0 + cb.x + p.t * wt.x);
                    v1 = ftanh(v1 + cb.y + p.t * wt.y);
                    unsigned lo, hi = pack_split2(v0, v1, lo);
                    ((unsigned*)p.Oh)[off >> 1] = hi;
                    ((unsigned*)p.Ol)[off >> 1] = lo;
                } else {
                    const float2 bi = *(const float2*)&p.bias[c];
                    v0 = ftanh(v0 + bi.x);
                    v1 = ftanh(v1 + bi.y);
                    unsigned lo, hi = pack_split2(v0, v1, lo);
                    ((unsigned*)p.Oh)[off >> 1] = hi;
                    ((unsigned*)p.Ol)[off >> 1] = lo;
                }
            }
        }
}

// ---------------- aux kernels ----------------
__device__ __forceinline__ void wsplit(float v, __nv_bfloat16* h, __nv_bfloat16* l, size_t i) {
    const __nv_bfloat16 hv = __float2bfloat16(v);
    h[i] = hv;
    l[i] = __float2bfloat16(v - __bfloat162float(hv));
}
__global__ void prep_k(const float* __restrict__ eps, const float* __restrict__ W2,
                       const float* __restrict__ W3, const float* __restrict__ W1,
                       __nv_bfloat16* eph, __nv_bfloat16* epl,
                       __half* w2f,
                       __nv_bfloat16* w3h, __nv_bfloat16* w3l,
                       __nv_bfloat16* w2th, __nv_bfloat16* w2tl,
                       __nv_bfloat16* w1yth, __nv_bfloat16* w1ytl,
                       __nv_bfloat16* w3th, __nv_bfloat16* w3tl) {
    int i = blockIdx.x * 256 + threadIdx.x;
    if (i < Bb * Dd) { wsplit(eps[i], eph, epl, i); return; }
    i -= Bb * Dd;
    if (i < Hh * Hh) { w2f[i] = __float2half_rn(W2[i]); return; }
    i -= Hh * Hh;
    if (i < Hh * Dd) { wsplit(W3[i], w3h, w3l, i); return; }
    i -= Hh * Dd;
    if (i < Hh * Hh) {
        const int r = i / Hh, c = i % Hh;
        wsplit(W2[i], w2th, w2tl, (size_t)c * Hh + r);
        return;
    }
    i -= Hh * Hh;
    if (i < Dd * Hh) {
        const int r = i / Hh, c = i % Hh;
        wsplit(W1[i], w1yth, w1ytl, (size_t)c * Dd + r);
        return;
    }
    i -= Dd * Hh;
    if (i < Hh * Dd) {
        const int r = i / Dd, c = i % Dd;
        wsplit(W3[i], w3th, w3tl, (size_t)c * Hh + r);
    }
}
__global__ void cbias_k(const float* __restrict__ cond, const float* __restrict__ W1c,
                        const float* __restrict__ b1, float* __restrict__ cb) {
    const int m = blockIdx.x;
    const int n = threadIdx.x * 4;
    float4 acc = *(const float4*)(b1 + n);
    #pragma unroll
    for (int k = 0; k < Cc; k++) {
        const float c = cond[m * Cc + k];
        const float4 w = *(const float4*)(W1c + (size_t)k * Hh + n);
        acc.x = fmaf(c, w.x, acc.x); acc.y = fmaf(c, w.y, acc.y);
        acc.z = fmaf(c, w.z, acc.z); acc.w = fmaf(c, w.w, acc.w);
    }
    *(float4*)(cb + (size_t)m * Hh + n) = acc;
}
__global__ void init_k(const float* __restrict__ x, float* __restrict__ y,
                       __nv_bfloat16* __restrict__ yinh, __nv_bfloat16* __restrict__ yinl,
                       float* __restrict__ ld) {
    const int i = blockIdx.x * blockDim.x + threadIdx.x;
    if (i < Bb * Dd) {
        const float v = x[i];
        y[i] = v;
        wsplit(v, yinh, yinl, i);
    }
    if (i < Bb) ld[i] = 0.f;
}
__global__ void out_k(const float* __restrict__ y, const float* __restrict__ ld,
                      const float* __restrict__ psum, float coef, float* __restrict__ out) {
    const int i = blockIdx.x * blockDim.x + threadIdx.x;
    if (i >= Bb * (Dd + 1)) return;
    const int m = i / (Dd + 1), c = i % (Dd + 1);
    if (c < Dd) {
        out[i] = y[(size_t)m * Dd + c];
    } else {
        float s = 0.f;
        #pragma unroll
        for (int c2 = 0; c2 < 8; c2++) s += psum[c2 * Bb + m];
        out[i] = ld[m] + coef * s;
    }
}

// ---------------- host ----------------
extern "C" void kernel_launch(void* const* d_in, const int* in_sizes, int n_in,
                              void* d_out, int out_size) {
    const float* x    = (const float*)d_in[0];
    const float* cond = (const float*)d_in[1];
    const float* eps  = (const float*)d_in[2];
    const float* W1   = (const float*)d_in[3];
    const float* b1   = (const float*)d_in[4];
    const float* W2   = (const float*)d_in[5];
    const float* b2   = (const float*)d_in[6];
    const float* W3   = (const float*)d_in[7];
    const float* b3   = (const float*)d_in[8];
    float* out = (float*)d_out;

    cudaFuncSetAttribute(mma_k<0>, cudaFuncAttributeMaxDynamicSharedMemorySize, SMEM_BYTES);
    cudaFuncSetAttribute(mma_k<1>, cudaFuncAttributeMaxDynamicSharedMemorySize, SMEM_BYTES);
    cudaFuncSetAttribute(mma_k<2>, cudaFuncAttributeMaxDynamicSharedMemorySize, SMEM_BYTES);
    cudaFuncSetAttribute(mma_k<3>, cudaFuncAttributeMaxDynamicSharedMemorySize, SMEM_BYTES);

    #define SYM(T, v, s) T* v; { void* _p; cudaGetSymbolAddress(&_p, s); v = (T*)_p; }
    SYM(float, y, g_y) SYM(float, yacc, g_yacc) SYM(float, cb, g_cb)
    SYM(float, G3, g_G3) SYM(float, E1, g_E1) SYM(float, ld, g_ld) SYM(float, psum, g_psum)
    SYM(__nv_bfloat16, h1h, g_h1h) SYM(__nv_bfloat16, h1l, g_h1l)
    SYM(__nv_bfloat16, h2h, g_h2h) SYM(__nv_bfloat16, h2l, g_h2l)
    SYM(__nv_bfloat16, yinh, g_yinh) SYM(__nv_bfloat16, yinl, g_yinl)
    SYM(__nv_bfloat16, epsh, g_epsh) SYM(__nv_bfloat16, epsl, g_epsl)
    SYM(__half, W2f, g_W2f)
    SYM(__nv_bfloat16, W2Th, g_W2Th) SYM(__nv_bfloat16, W2Tl, g_W2Tl)
    SYM(__nv_bfloat16, W3h, g_W3h) SYM(__nv_bfloat16, W3l, g_W3l)
    SYM(__nv_bfloat16, W3Th, g_W3Th) SYM(__nv_bfloat16, W3Tl, g_W3Tl)
    SYM(__nv_bfloat16, W1yTh, g_W1yTh) SYM(__nv_bfloat16, W1yTl, g_W1yTl)
    #undef SYM

    init_k<<<(Bb * Dd + 255) / 256, 256>>>(x, y, yinh, yinl, ld);

    constexpr int PREP_N = Bb * Dd + Hh * Hh + Hh * Dd + Hh * Hh + Dd * Hh + Hh * Dd;
    const float dt = 1.0f / NS;
    float prev_cl = 0.f;

    for (int ib = 0; ib < NB; ib++) {
        const float* W1b  = W1 + (size_t)ib * (Dd + Cc + 1) * Hh;
        const float* b1b  = b1 + (size_t)ib * Hh;
        const float* W2b  = W2 + (size_t)ib * Hh * Hh;
        const float* b2b  = b2 + (size_t)ib * Hh;
        const float* W3b  = W3 + (size_t)ib * Hh * Dd;
        const float* b3b  = b3 + (size_t)ib * Dd;
        const float* epsb = eps + (size_t)ib * Bb * Dd;
        float* cbb = cb + (size_t)ib * Bb * Hh;
        float* G3b = G3 + (size_t)ib * Bb * Hh;
        float* E1b = E1 + (size_t)ib * Bb * Hh;
        __nv_bfloat16 *eph = epsh + (size_t)ib * Bb * Dd, *epl = epsl + (size_t)ib * Bb * Dd;
        __half* w2f = W2f + (size_t)ib * Hh * Hh;
        __nv_bfloat16 *w2th = W2Th + (size_t)ib * Hh * Hh, *w2tl = W2Tl + (size_t)ib * Hh * Hh;
        __nv_bfloat16 *w3h = W3h + (size_t)ib * Hh * Dd, *w3l = W3l + (size_t)ib * Hh * Dd;
        __nv_bfloat16 *w3th = W3Th + (size_t)ib * Dd * Hh, *w3tl = W3Tl + (size_t)ib * Dd * Hh;
        __nv_bfloat16 *w1yth = W1yTh + (size_t)ib * Hh * Dd, *w1ytl = W1yTl + (size_t)ib * Hh * Dd;

        prep_k<<<(PREP_N + 255) / 256, 256>>>(epsb, W2b, W3b, W1b,
            eph, epl, w2f, w3h, w3l, w2th, w2tl, w1yth, w1ytl, w3th, w3tl);
        cbias_k<<<Bb, 128>>>(cond, W1b + (size_t)Dd * Hh, b1b, cbb);

        {   // merged G3 (by<8) + E1 (by>=8)
            P p{}; p.Ah = eph; p.Al = epl;
            p.Bh = w3h; p.Bl = w3l; p.C = G3b;
            p.B2h = w1yth; p.B2l = w1ytl; p.C2 = E1b;
            mma_k<0><<<dim3(32, 16), 256, SMEM_BYTES>>>(p);
        }

        for (int is = 0; is < NS; is++) {
            const float tbase = is * dt;
            for (int st = 1; st <= 4; st++) {
                const float t = tbase + (st == 1 ? 0.f : (st == 4 ? dt : 0.5f * dt));
                const float cacc = (st == 1 || st == 4) ? dt / 6.f : dt / 3.f;
                const float cin  = (st == 3) ? dt : 0.5f * dt;

                {   // F1 + fold rider
                    P p{}; p.Ah = yinh; p.Al = yinl; p.Bh = w1yth; p.Bl = w1ytl;
                    p.cbias = cbb; p.w1t = W1b + (size_t)(Dd + Cc) * Hh; p.t = t;
                    p.Oh = h1h; p.Ol = h1l;
                    p.foldcoef = prev_cl; p.ld = ld; p.psum = psum;
                    mma_k<1><<<dim3(32, 9), 256, SMEM_BYTES>>>(p);
                }
                {   // F2
                    P p{}; p.Ah = h1h; p.Al = h1l; p.Bh = w2th; p.Bl = w2tl;
                    p.bias = b2b; p.Oh = h2h; p.Ol = h2l;
                    mma_k<2><<<dim3(32, 8), 256, SMEM_BYTES>>>(p);
                }
                {   // FUSED: B2 single-fp16 + logdet dot (by<8), F3 + RK4 (by==8)
                    P p{};
                    p.Amask = G3b; p.Mh = h2h; p.Ml = h2l; p.W2f = w2f;
                    p.F3Ah = h2h; p.F3Al = h2l; p.F3Bh = w3th; p.F3Bl = w3tl;
                    p.h1h = h1h; p.h1l = h1l; p.E1 = E1b; p.psum = psum;
                    p.b3 = b3b; p.y = y; p.yacc = yacc; p.Oh = yinh; p.Ol = yinl;
                    p.stage = st; p.cacc = cacc; p.cin = cin;
                    mma_k<3><<<dim3(32, 9), 256, SMEM_BYTES>>>(p);
                }
                prev_cl = cacc;
            }
        }
    }

    out_k<<<(Bb * (Dd + 1) + 255) / 256, 256>>>(y, ld, psum, prev_cl, out);
}